// round 6
// baseline (speedup 1.0000x reference)
#include <cuda_runtime.h>
#include <cstdint>
#include <math_constants.h>

// Problem constants
#define B_   4
#define C_   84
#define CP_  80        // channels used for the max (points[:, :-4])
#define H_   512
#define W_   512
#define HW_  (H_ * W_)        // 262144
#define NROWS (B_ * H_)       // 2048

#define COLS    256            // columns per CTA (half row)
#define NSEG    2              // segments per row
#define THREADS 256

// Global scratch: probs rows + per-row "segments published" counters
__device__ float g_probs[NROWS * W_];
__device__ int   g_flags[NROWS];

__device__ __forceinline__ int ld_acquire(const int* p) {
    int v;
    asm volatile("ld.acquire.gpu.s32 %0, [%1];" : "=r"(v) : "l"(p));
    return v;
}

__global__ void clear_flags_kernel() {
    int t = blockIdx.x * blockDim.x + threadIdx.x;
    if (t < NROWS) g_flags[t] = 0;
}

// ---------------------------------------------------------------------------
// Fused NMS, L2-reuse version. One CTA per (row, half): 84 ch x 256 cols.
//  A) LDG-stream 80 channels, register max (4 accumulators, deep MLP)
//  B) publish probs segment to g_probs; bump row counter
//  C) wait rows r-1, r, r+1 complete; stage halo rows in smem; 3x3 mask
//  D) re-read all 84 channels via float4 LDG (L2-hot), multiply, STG out
// ---------------------------------------------------------------------------
__global__ __launch_bounds__(THREADS) void nms_fused_kernel(
    const float* __restrict__ pts, float* __restrict__ out) {
    // 16B-aligned, 260-float arrays so every block stays 16B aligned.
    __shared__ __align__(16) float up_s[COLS + 4];
    __shared__ __align__(16) float mid_s[COLS + 4];
    __shared__ __align__(16) float dn_s[COLS + 4];
    __shared__ __align__(16) float mask_s[COLS];

    const int tid = threadIdx.x;
    const int cta = blockIdx.x;
    const int r   = cta >> 1;              // row id: b*H + i
    const int seg = cta & 1;
    const int b   = r >> 9;
    const int i   = r & (H_ - 1);
    const int c0  = seg * COLS;

    // ---- Phase A: channel max over first 80, column c0+tid ----
    {
        const float* base = pts + (size_t)b * C_ * HW_ + (size_t)i * W_ + c0 + tid;
        float p0 = -CUDART_INF_F, p1 = -CUDART_INF_F;
        float p2 = -CUDART_INF_F, p3 = -CUDART_INF_F;
        #pragma unroll 5
        for (int c = 0; c < CP_; c += 4) {
            float v0 = base[(size_t)(c    ) * HW_];
            float v1 = base[(size_t)(c + 1) * HW_];
            float v2 = base[(size_t)(c + 2) * HW_];
            float v3 = base[(size_t)(c + 3) * HW_];
            p0 = fmaxf(p0, v0);
            p1 = fmaxf(p1, v1);
            p2 = fmaxf(p2, v2);
            p3 = fmaxf(p3, v3);
        }
        float p = fmaxf(fmaxf(p0, p1), fmaxf(p2, p3));
        g_probs[(size_t)r * W_ + c0 + tid] = p;
        mid_s[tid + 1] = p;
    }
    __threadfence();
    __syncthreads();
    if (tid == 0) atomicAdd(&g_flags[r], 1);

    // ---- Phase C: wait for rows r-1, r, r+1 fully published ----
    if (tid == 0) {
        const int* f = &g_flags[r];
        while (ld_acquire(f) < NSEG) __nanosleep(32);
    }
    if (tid == 32 && i > 0) {
        const int* f = &g_flags[r - 1];
        while (ld_acquire(f) < NSEG) __nanosleep(32);
    }
    if (tid == 64 && i < H_ - 1) {
        const int* f = &g_flags[r + 1];
        while (ld_acquire(f) < NSEG) __nanosleep(32);
    }
    __syncthreads();

    // stage halo rows (L2-hot reads of g_probs)
    for (int idx = tid; idx < COLS + 2; idx += THREADS) {
        int gcol = c0 - 1 + idx;
        bool cok = (gcol >= 0) & (gcol < W_);
        up_s[idx] = (cok && i > 0)      ? g_probs[(size_t)(r - 1) * W_ + gcol] : 0.0f;
        dn_s[idx] = (cok && i < H_ - 1) ? g_probs[(size_t)(r + 1) * W_ + gcol] : 0.0f;
        if (idx == 0 || idx == COLS + 1)
            mid_s[idx] = cok ? g_probs[(size_t)r * W_ + gcol] : 0.0f;
    }
    __syncthreads();

    {
        int w = tid;
        float p = mid_s[w + 1];
        // strict > for neighbors before center (up row, mid-left),
        // >= for after (mid-right, down row); OOB = 0 (zero padding)
        bool ok = (p >  up_s[w]) & (p >  up_s[w + 1]) & (p >  up_s[w + 2])
                & (p >  mid_s[w]) & (p >= mid_s[w + 2])
                & (p >= dn_s[w]) & (p >= dn_s[w + 1]) & (p >= dn_s[w + 2]);
        mask_s[w] = ok ? 1.0f : 0.0f;
    }
    __syncthreads();

    // ---- Phase D: re-read (L2-hot) all 84 channels, multiply, store ----
    {
        const int COLS4 = COLS / 4;                       // 64
        const float4* src = reinterpret_cast<const float4*>(pts)
                          + ((size_t)b * C_ * HW_ + (size_t)i * W_ + c0) / 4;
        float4* dst = reinterpret_cast<float4*>(out)
                    + ((size_t)b * C_ * HW_ + (size_t)i * W_ + c0) / 4;
        const float4* mask4 = reinterpret_cast<const float4*>(mask_s);
        const int HW4 = HW_ / 4;
        #pragma unroll 3
        for (int k = tid; k < C_ * COLS4; k += THREADS) {
            int c = k >> 6;                               // / 64
            int j = k & (COLS4 - 1);
            float4 v = src[(size_t)c * HW4 + j];
            float4 m = mask4[j];
            v.x *= m.x; v.y *= m.y; v.z *= m.z; v.w *= m.w;
            dst[(size_t)c * HW4 + j] = v;
        }
    }
}

extern "C" void kernel_launch(void* const* d_in, const int* in_sizes, int n_in,
                              void* d_out, int out_size) {
    const float* pts = (const float*)d_in[0];
    float* out = (float*)d_out;

    clear_flags_kernel<<<(NROWS + 511) / 512, 512>>>();
    nms_fused_kernel<<<NROWS * NSEG, THREADS>>>(pts, out);
}

// round 7
// speedup vs baseline: 1.0613x; 1.0613x over previous
#include <cuda_runtime.h>
#include <cstdint>
#include <math_constants.h>

// Problem constants
#define B_   4
#define C_   84
#define CP_  80        // channels used for the max (points[:, :-4])
#define H_   512
#define W_   512
#define HW_  (H_ * W_)        // 262144
#define NROWS (B_ * H_)       // 2048

#define COLS    128            // columns per CTA (one thread per column)
#define NSEG    4              // segments per row
#define THREADS 128

// Global scratch: probs rows, per-row publish counters, per-row consume counters.
// All zero-initialized at module load; the kernel self-cleans flags/done so
// every graph replay starts from the zero state again.
__device__ float g_probs[NROWS * W_];
__device__ int   g_flags[NROWS];
__device__ int   g_done[NROWS];

__device__ __forceinline__ int ld_acquire(const int* p) {
    int v;
    asm volatile("ld.acquire.gpu.s32 %0, [%1];" : "=r"(v) : "l"(p));
    return v;
}

// Called once per (consumer CTA, consumed row) AFTER all g_probs reads of that
// row by this CTA have completed. The final consumer resets the row's state.
__device__ __forceinline__ void consume_row(int rr, int ii) {
    int need = NSEG * (1 + (ii > 0) + (ii < H_ - 1));
    int prev = atomicAdd(&g_done[rr], 1);
    if (prev + 1 == need) {
        g_flags[rr] = 0;
        g_done[rr]  = 0;
    }
}

// ---------------------------------------------------------------------------
// Fused NMS, register-resident tile. One CTA per (row, quarter).
// Each thread owns ONE column: loads all 84 channels into registers (points
// read exactly once), max-reduces the first 80, publishes its probs value,
// syncs with neighbor rows, computes its own mask bit, multiplies the
// register tile and streams it out. DRAM traffic = algorithmic minimum.
// ---------------------------------------------------------------------------
__global__ __launch_bounds__(THREADS, 4) void nms_fused_kernel(
    const float* __restrict__ pts, float* __restrict__ out) {
    __shared__ float up_s[COLS + 2];
    __shared__ float mid_s[COLS + 2];
    __shared__ float dn_s[COLS + 2];

    const int tid = threadIdx.x;
    const int cta = blockIdx.x;
    const int r   = cta >> 2;              // row id: b*H + i
    const int seg = cta & 3;
    const int b   = r >> 9;
    const int i   = r & (H_ - 1);
    const int c0  = seg * COLS;

    const size_t base_off = (size_t)b * C_ * HW_ + (size_t)i * W_ + c0 + tid;
    const float* base = pts + base_off;

    // ---- Phase A: load all 84 channels into registers (single read) ----
    float v[C_];
    #pragma unroll
    for (int c = 0; c < C_; c++) v[c] = base[(size_t)c * HW_];

    // channel max over first 80
    float p = v[0];
    #pragma unroll
    for (int c = 1; c < CP_; c++) p = fmaxf(p, v[c]);

    g_probs[(size_t)r * W_ + c0 + tid] = p;
    mid_s[tid + 1] = p;
    __threadfence();
    __syncthreads();
    if (tid == 0) atomicAdd(&g_flags[r], 1);

    // ---- Phase B: wait for rows r-1, r, r+1 fully published ----
    if (tid == 0) {
        while (ld_acquire(&g_flags[r]) < NSEG) __nanosleep(32);
    }
    if (tid == 32 && i > 0) {
        while (ld_acquire(&g_flags[r - 1]) < NSEG) __nanosleep(32);
    }
    if (tid == 64 && i < H_ - 1) {
        while (ld_acquire(&g_flags[r + 1]) < NSEG) __nanosleep(32);
    }
    __syncthreads();

    // stage halo rows from g_probs (L2-hot)
    for (int idx = tid; idx < COLS + 2; idx += THREADS) {
        int gcol = c0 - 1 + idx;
        bool cok = (gcol >= 0) & (gcol < W_);
        up_s[idx] = (cok && i > 0)      ? g_probs[(size_t)(r - 1) * W_ + gcol] : 0.0f;
        dn_s[idx] = (cok && i < H_ - 1) ? g_probs[(size_t)(r + 1) * W_ + gcol] : 0.0f;
        if (idx == 0 || idx == COLS + 1)
            mid_s[idx] = cok ? g_probs[(size_t)r * W_ + gcol] : 0.0f;
    }
    __syncthreads();

    // all g_probs reads done -> signal consumption (self-cleaning flags)
    if (tid == 0)               consume_row(r, i);
    if (tid == 32 && i > 0)     consume_row(r - 1, i - 1);
    if (tid == 64 && i < H_ - 1) consume_row(r + 1, i + 1);

    // ---- Phase C: per-thread mask bit ----
    // strict > for neighbors before center (up row, mid-left),
    // >= for after (mid-right, down row); OOB = 0 (zero padding)
    const int w = tid;
    const float pc = mid_s[w + 1];
    bool ok = (pc >  up_s[w]) & (pc >  up_s[w + 1]) & (pc >  up_s[w + 2])
            & (pc >  mid_s[w]) & (pc >= mid_s[w + 2])
            & (pc >= dn_s[w]) & (pc >= dn_s[w + 1]) & (pc >= dn_s[w + 2]);
    const float m = ok ? 1.0f : 0.0f;

    // ---- Phase D: multiply register tile, stream out ----
    float* dst = out + base_off;
    #pragma unroll
    for (int c = 0; c < C_; c++) dst[(size_t)c * HW_] = v[c] * m;
}

extern "C" void kernel_launch(void* const* d_in, const int* in_sizes, int n_in,
                              void* d_out, int out_size) {
    const float* pts = (const float*)d_in[0];
    float* out = (float*)d_out;

    nms_fused_kernel<<<NROWS * NSEG, THREADS>>>(pts, out);
}

// round 9
// speedup vs baseline: 1.1836x; 1.1153x over previous
#include <cuda_runtime.h>
#include <cstdint>
#include <math_constants.h>

// Problem constants
#define B_   4
#define C_   84
#define CP_  80        // channels used for the max (points[:, :-4])
#define H_   512
#define W_   512
#define HW_  (H_ * W_)        // 262144
#define NROWS (B_ * H_)       // 2048

#define COLS    128            // columns per CTA (one thread per column)
#define NSEG    4              // segments per row
#define THREADS 128

#define RCH     36             // channels held in registers  (0..35)
#define SCH     (C_ - RCH)     // channels held in smem       (36..83) = 48
#define SMAX    (CP_ - RCH)    // smem channels entering max  (36..79) = 44

// Global scratch: probs rows, publish counters, consume counters.
// Zero at module load; kernel self-cleans so graph replays see zero again.
__device__ float g_probs[NROWS * W_];
__device__ int   g_flags[NROWS];
__device__ int   g_done[NROWS];

__device__ __forceinline__ int ld_acquire(const int* p) {
    int v;
    asm volatile("ld.acquire.gpu.s32 %0, [%1];" : "=r"(v) : "l"(p));
    return v;
}

// Called once per (consumer CTA, consumed row) AFTER all g_probs reads of that
// row by this CTA. The final consumer resets the row's state for next replay.
__device__ __forceinline__ void consume_row(int rr, int ii) {
    int need = NSEG * (1 + (ii > 0) + (ii < H_ - 1));
    int prev = atomicAdd(&g_done[rr], 1);
    if (prev + 1 == need) {
        g_flags[rr] = 0;
        g_done[rr]  = 0;
    }
}

// ---------------------------------------------------------------------------
// Fused NMS, split register/smem tile. One CTA per (row, quarter).
// points is read exactly once (36 ch in regs, 48 ch in smem); ~27KB smem and
// <=64 regs give 8 CTAs/SM so load/store phases of different CTAs overlap.
// ---------------------------------------------------------------------------
__global__ __launch_bounds__(THREADS, 8) void nms_fused_kernel(
    const float* __restrict__ pts, float* __restrict__ out) {
    __shared__ __align__(16) float tile[SCH * COLS];       // 24 KB
    __shared__ __align__(16) float up_s[COLS + 4];
    __shared__ __align__(16) float mid_s[COLS + 4];
    __shared__ __align__(16) float dn_s[COLS + 4];
    __shared__ __align__(16) float mask_s[COLS];

    const int tid = threadIdx.x;
    const int cta = blockIdx.x;
    const int r   = cta >> 2;              // row id: b*H + i
    const int seg = cta & 3;
    const int b   = r >> 9;
    const int i   = r & (H_ - 1);
    const int c0  = seg * COLS;

    const size_t row_off = (size_t)b * C_ * HW_ + (size_t)i * W_ + c0;

    // ---- Phase A1: cooperative float4 load of smem channels 36..83 ----
    #pragma unroll
    for (int it = 0; it < SCH / 4; it++) {                 // 12 iters
        int idx  = it * THREADS + tid;
        int chl  = idx >> 5;                               // 0..47
        int col4 = (idx & 31) << 2;                        // 0,4,..,124
        float4 x = *reinterpret_cast<const float4*>(
            pts + row_off + (size_t)(RCH + chl) * HW_ + col4);
        *reinterpret_cast<float4*>(&tile[chl * COLS + col4]) = x;
    }

    // ---- Phase A2: register channels 0..35, max on the fly ----
    const float* base = pts + row_off + tid;
    float v[RCH];
    float p = -CUDART_INF_F;
    #pragma unroll
    for (int c = 0; c < RCH; c++) {
        v[c] = base[(size_t)c * HW_];
        p = fmaxf(p, v[c]);
    }
    __syncthreads();

    // max over smem channels 36..79 (local 0..43), conflict-free LDS
    #pragma unroll 11
    for (int chl = 0; chl < SMAX; chl++)
        p = fmaxf(p, tile[chl * COLS + tid]);

    g_probs[(size_t)r * W_ + c0 + tid] = p;
    mid_s[tid + 1] = p;
    __threadfence();
    __syncthreads();
    if (tid == 0) atomicAdd(&g_flags[r], 1);

    // ---- Phase B: wait for rows r-1, r, r+1 fully published ----
    if (tid == 0) {
        while (ld_acquire(&g_flags[r]) < NSEG) __nanosleep(32);
    }
    if (tid == 32 && i > 0) {
        while (ld_acquire(&g_flags[r - 1]) < NSEG) __nanosleep(32);
    }
    if (tid == 64 && i < H_ - 1) {
        while (ld_acquire(&g_flags[r + 1]) < NSEG) __nanosleep(32);
    }
    __syncthreads();

    // stage halo rows from g_probs (L2-hot)
    for (int idx = tid; idx < COLS + 2; idx += THREADS) {
        int gcol = c0 - 1 + idx;
        bool cok = (gcol >= 0) & (gcol < W_);
        up_s[idx] = (cok && i > 0)      ? g_probs[(size_t)(r - 1) * W_ + gcol] : 0.0f;
        dn_s[idx] = (cok && i < H_ - 1) ? g_probs[(size_t)(r + 1) * W_ + gcol] : 0.0f;
        if (idx == 0 || idx == COLS + 1)
            mid_s[idx] = cok ? g_probs[(size_t)r * W_ + gcol] : 0.0f;
    }
    __syncthreads();

    // all g_probs reads done -> mark consumed (self-cleaning flags)
    if (tid == 0)                consume_row(r, i);
    if (tid == 32 && i > 0)      consume_row(r - 1, i - 1);
    if (tid == 64 && i < H_ - 1) consume_row(r + 1, i + 1);

    // ---- Phase C: per-column mask bit ----
    // strict > for neighbors before center (up row, mid-left),
    // >= for after (mid-right, down row); OOB = 0 (zero padding)
    {
        const int w = tid;
        const float pc = mid_s[w + 1];
        bool ok = (pc >  up_s[w]) & (pc >  up_s[w + 1]) & (pc >  up_s[w + 2])
                & (pc >  mid_s[w]) & (pc >= mid_s[w + 2])
                & (pc >= dn_s[w]) & (pc >= dn_s[w + 1]) & (pc >= dn_s[w + 2]);
        mask_s[w] = ok ? 1.0f : 0.0f;
    }
    __syncthreads();

    // ---- Phase D: multiply + store ----
    const float m = mask_s[tid];
    float* dstb = out + row_off + tid;
    #pragma unroll
    for (int c = 0; c < RCH; c++)
        dstb[(size_t)c * HW_] = v[c] * m;

    const float4* mask4 = reinterpret_cast<const float4*>(mask_s);
    #pragma unroll
    for (int it = 0; it < SCH / 4; it++) {                 // 12 iters
        int idx  = it * THREADS + tid;
        int chl  = idx >> 5;
        int col4i = idx & 31;
        int col4 = col4i << 2;
        float4 x = *reinterpret_cast<const float4*>(&tile[chl * COLS + col4]);
        float4 mm = mask4[col4i];
        x.x *= mm.x; x.y *= mm.y; x.z *= mm.z; x.w *= mm.w;
        *reinterpret_cast<float4*>(
            out + row_off + (size_t)(RCH + chl) * HW_ + col4) = x;
    }
}

extern "C" void kernel_launch(void* const* d_in, const int* in_sizes, int n_in,
                              void* d_out, int out_size) {
    const float* pts = (const float*)d_in[0];
    float* out = (float*)d_out;

    nms_fused_kernel<<<NROWS * NSEG, THREADS>>>(pts, out);
}